// round 2
// baseline (speedup 1.0000x reference)
#include <cuda_runtime.h>

#define NN 400000
#define NG 1000
#define FEAT 240
#define NSEG 4

__device__ int g_cnt[NG];
__device__ int g_off[NG];
__device__ int g_cur[NG];
__device__ int g_order[NN];
__device__ float g_part[NG * NSEG * 944];

__global__ void k_zero() {
    int i = blockIdx.x * blockDim.x + threadIdx.x;
    if (i < NG) g_cnt[i] = 0;
}

__global__ void k_hist(const int4* __restrict__ idx) {
    int i = blockIdx.x * blockDim.x + threadIdx.x;
    if (i < NN / 4) {
        int4 v = idx[i];
        atomicAdd(&g_cnt[v.x], 1);
        atomicAdd(&g_cnt[v.y], 1);
        atomicAdd(&g_cnt[v.z], 1);
        atomicAdd(&g_cnt[v.w], 1);
    }
}

__global__ void k_scan() {
    __shared__ int s[1024];
    int tid = threadIdx.x;
    int v = (tid < NG) ? g_cnt[tid] : 0;
    s[tid] = v;
    __syncthreads();
    for (int off = 1; off < 1024; off <<= 1) {
        int t = (tid >= off) ? s[tid - off] : 0;
        __syncthreads();
        s[tid] += t;
        __syncthreads();
    }
    if (tid < NG) {
        int excl = s[tid] - v;
        g_off[tid] = excl;
        g_cur[tid] = excl;
    }
}

__global__ void k_scatter(const int4* __restrict__ idx) {
    int i = blockIdx.x * blockDim.x + threadIdx.x;
    if (i < NN / 4) {
        int4 v = idx[i];
        int base = 4 * i;
        int p0 = atomicAdd(&g_cur[v.x], 1);
        int p1 = atomicAdd(&g_cur[v.y], 1);
        int p2 = atomicAdd(&g_cur[v.z], 1);
        int p3 = atomicAdd(&g_cur[v.w], 1);
        g_order[p0] = base;
        g_order[p1] = base + 1;
        g_order[p2] = base + 2;
        g_order[p3] = base + 3;
    }
}

// Partial-sum layout (944 floats per (graph, segment)):
//   [0,240)    sum(x)
//   [240,480)  sum(x * e^{+norm})
//   [480,720)  sum(x * e^{-norm})
//   [720,832)  sum(e^{+norm})   (112 irrep instances: 64 l0, 32 l1, 16 l2)
//   [832,944)  sum(e^{-norm})
// Block = 256 threads = 4 node-groups of 64 lanes. Lane u of a group owns:
//   l0 channel u; if u<32 the l1 triple at 64+3u; if 32<=u<48 the l2
//   quintuple at 160+5(u-32).
__global__ void __launch_bounds__(256, 6) k_partial(const float* __restrict__ x)
{
    __shared__ float s_part[4][944];

    const int g = blockIdx.x;
    const int seg = blockIdx.y;
    const int tid = threadIdx.x;
    const int grp = tid >> 6;
    const int u = tid & 63;
    const int start = g_off[g];
    const int cnt = g_cnt[g];
    const int j0 = (cnt * seg) >> 2;
    const int j1 = (cnt * (seg + 1)) >> 2;
    const bool isC = (u < 32);
    const bool isD = (u >= 32) && (u < 48);
    const int t = u - 32;

    float sa = 0.f, pa = 0.f, ma = 0.f, zpa = 0.f, zma = 0.f;
    float sc0 = 0.f, sc1 = 0.f, sc2 = 0.f;
    float pc0 = 0.f, pc1 = 0.f, pc2 = 0.f;
    float mc0 = 0.f, mc1 = 0.f, mc2 = 0.f;
    float zpc = 0.f, zmc = 0.f;
    float sd0 = 0.f, sd1 = 0.f, sd2 = 0.f, sd3 = 0.f, sd4 = 0.f;
    float pd0 = 0.f, pd1 = 0.f, pd2 = 0.f, pd3 = 0.f, pd4 = 0.f;
    float md0 = 0.f, md1 = 0.f, md2 = 0.f, md3 = 0.f, md4 = 0.f;
    float zpd = 0.f, zmd = 0.f;

    int j = j0 + grp;
    int node = (j < j1) ? g_order[start + j] : 0;
    while (j < j1) {
        const float* r = x + (long long)node * FEAT;
        const int jn = j + 4;
        const int nnode = (jn < j1) ? g_order[start + jn] : 0;

        float a = __ldg(r + u);
        float c0 = 0.f, c1 = 0.f, c2 = 0.f;
        float d0 = 0.f, d1 = 0.f, d2 = 0.f, d3 = 0.f, d4 = 0.f;
        if (isC) {
            c0 = __ldg(r + 64 + 3 * u);
            c1 = __ldg(r + 65 + 3 * u);
            c2 = __ldg(r + 66 + 3 * u);
        }
        if (isD) {
            const float* q = r + 160 + 5 * t;
            d0 = __ldg(q + 0); d1 = __ldg(q + 1); d2 = __ldg(q + 2);
            d3 = __ldg(q + 3); d4 = __ldg(q + 4);
        }

        float na = fabsf(a);
        float ea = __expf(na), ra = __expf(-na);
        sa += a; pa += a * ea; ma += a * ra;
        zpa += ea; zma += ra;

        if (isC) {
            float nc = sqrtf(c0 * c0 + c1 * c1 + c2 * c2);
            float ec = __expf(nc), rc = __expf(-nc);
            sc0 += c0; sc1 += c1; sc2 += c2;
            pc0 += c0 * ec; pc1 += c1 * ec; pc2 += c2 * ec;
            mc0 += c0 * rc; mc1 += c1 * rc; mc2 += c2 * rc;
            zpc += ec; zmc += rc;
        }
        if (isD) {
            float nd = sqrtf(d0 * d0 + d1 * d1 + d2 * d2 + d3 * d3 + d4 * d4);
            float ed = __expf(nd), rd = __expf(-nd);
            sd0 += d0; sd1 += d1; sd2 += d2; sd3 += d3; sd4 += d4;
            pd0 += d0 * ed; pd1 += d1 * ed; pd2 += d2 * ed;
            pd3 += d3 * ed; pd4 += d4 * ed;
            md0 += d0 * rd; md1 += d1 * rd; md2 += d2 * rd;
            md3 += d3 * rd; md4 += d4 * rd;
            zpd += ed; zmd += rd;
        }
        j = jn; node = nnode;
    }

    {
        float* P = s_part[grp];
        P[u] = sa;       P[240 + u] = pa;  P[480 + u] = ma;
        P[720 + u] = zpa; P[832 + u] = zma;
        if (isC) {
            P[64 + 3 * u + 0] = sc0; P[64 + 3 * u + 1] = sc1; P[64 + 3 * u + 2] = sc2;
            P[304 + 3 * u + 0] = pc0; P[304 + 3 * u + 1] = pc1; P[304 + 3 * u + 2] = pc2;
            P[544 + 3 * u + 0] = mc0; P[544 + 3 * u + 1] = mc1; P[544 + 3 * u + 2] = mc2;
            P[784 + u] = zpc; P[896 + u] = zmc;
        }
        if (isD) {
            P[160 + 5 * t + 0] = sd0; P[160 + 5 * t + 1] = sd1; P[160 + 5 * t + 2] = sd2;
            P[160 + 5 * t + 3] = sd3; P[160 + 5 * t + 4] = sd4;
            P[400 + 5 * t + 0] = pd0; P[400 + 5 * t + 1] = pd1; P[400 + 5 * t + 2] = pd2;
            P[400 + 5 * t + 3] = pd3; P[400 + 5 * t + 4] = pd4;
            P[640 + 5 * t + 0] = md0; P[640 + 5 * t + 1] = md1; P[640 + 5 * t + 2] = md2;
            P[640 + 5 * t + 3] = md3; P[640 + 5 * t + 4] = md4;
            P[816 + t] = zpd; P[928 + t] = zmd;
        }
    }
    __syncthreads();

    float* dst = g_part + (g * NSEG + seg) * 944;
    for (int f = tid; f < 944; f += 256) {
        dst[f] = s_part[0][f] + s_part[1][f] + s_part[2][f] + s_part[3][f];
    }
}

__global__ void __launch_bounds__(256) k_finish(
    const float* __restrict__ W0, const float* __restrict__ W1,
    const float* __restrict__ W2, const float* __restrict__ b0,
    float* __restrict__ out)
{
    __shared__ float s_tot[944];
    __shared__ float s_pool[3][240];

    const int g = blockIdx.x;
    const int tid = threadIdx.x;
    const int cnt = g_cnt[g];
    const float* src = g_part + g * NSEG * 944;

    for (int f = tid; f < 944; f += 256) {
        float acc = 0.f;
        #pragma unroll
        for (int s = 0; s < NSEG; s++) acc += src[s * 944 + f];
        s_tot[f] = acc;
    }
    __syncthreads();

    const float invc = (cnt > 0) ? (1.0f / (float)cnt) : 0.0f;
    for (int f = tid; f < 240; f += 256) {
        int k;
        if (f < 64)       k = f;
        else if (f < 160) k = 64 + (f - 64) / 3;
        else              k = 96 + (f - 160) / 5;
        float zp = s_tot[720 + k];
        float zm = s_tot[832 + k];
        float rzp = (zp > 0.f) ? 1.0f / zp : 0.f;
        float rzm = (zm > 0.f) ? 1.0f / zm : 0.f;
        s_pool[0][f] = s_tot[f] * invc;
        s_pool[1][f] = s_tot[240 + f] * rzp;
        s_pool[2][f] = s_tot[480 + f] * rzm;
    }
    __syncthreads();

    // Per-graph o3.Linear: cat(mean, max, min) per l, W contraction, 1/sqrt(3*mul)
    if (tid < 240) {
        float o = 0.f;
        if (tid < 64) {
            const int f = tid;
            #pragma unroll 8
            for (int i = 0; i < 64; i++) {
                o += s_pool[0][i] * __ldg(W0 + i * 64 + f);
                o += s_pool[1][i] * __ldg(W0 + (64 + i) * 64 + f);
                o += s_pool[2][i] * __ldg(W0 + (128 + i) * 64 + f);
            }
            o = o * 0.07216878364870323f + __ldg(b0 + f);   // 1/sqrt(192)
            out[g * FEAT + f] = o;
        } else if (tid < 160) {
            const int ff = tid - 64;
            const int oo = ff / 3, dd = ff % 3;
            #pragma unroll 8
            for (int i = 0; i < 32; i++) {
                o += s_pool[0][64 + 3 * i + dd] * __ldg(W1 + i * 32 + oo);
                o += s_pool[1][64 + 3 * i + dd] * __ldg(W1 + (32 + i) * 32 + oo);
                o += s_pool[2][64 + 3 * i + dd] * __ldg(W1 + (64 + i) * 32 + oo);
            }
            out[g * FEAT + tid] = o * 0.10206207261596575f; // 1/sqrt(96)
        } else {
            const int ff = tid - 160;
            const int oo = ff / 5, dd = ff % 5;
            #pragma unroll
            for (int i = 0; i < 16; i++) {
                o += s_pool[0][160 + 5 * i + dd] * __ldg(W2 + i * 16 + oo);
                o += s_pool[1][160 + 5 * i + dd] * __ldg(W2 + (16 + i) * 16 + oo);
                o += s_pool[2][160 + 5 * i + dd] * __ldg(W2 + (32 + i) * 16 + oo);
            }
            out[g * FEAT + tid] = o * 0.14433756729740643f; // 1/sqrt(48)
        }
    }
}

extern "C" void kernel_launch(void* const* d_in, const int* in_sizes, int n_in,
                              void* d_out, int out_size) {
    const float* x = nullptr;
    const int* idx = nullptr;
    const float *W0 = nullptr, *W1 = nullptr, *W2 = nullptr, *b0 = nullptr;
    for (int i = 0; i < n_in; i++) {
        switch (in_sizes[i]) {
            case 96000000: x   = (const float*)d_in[i]; break; // x [400000,240]
            case 400000:   idx = (const int*)d_in[i];   break; // index
            case 12288:    W0  = (const float*)d_in[i]; break; // [192,64]
            case 3072:     W1  = (const float*)d_in[i]; break; // [96,32]
            case 768:      W2  = (const float*)d_in[i]; break; // [48,16]
            case 64:       b0  = (const float*)d_in[i]; break; // [64]
            default: break; // dim_size scalar etc.
        }
    }
    k_zero<<<1, 1024>>>();
    k_hist<<<(NN / 4 + 255) / 256, 256>>>((const int4*)idx);
    k_scan<<<1, 1024>>>();
    k_scatter<<<(NN / 4 + 255) / 256, 256>>>((const int4*)idx);
    k_partial<<<dim3(NG, NSEG), 256>>>(x);
    k_finish<<<NG, 256>>>(W0, W1, W2, b0, (float*)d_out);
}

// round 3
// speedup vs baseline: 1.8620x; 1.8620x over previous
#include <cuda_runtime.h>

#define NN 400000
#define NG 1000
#define FEAT 240
#define NSEG 4
#define CH 4096
#define NB ((NN + CH - 1) / CH)   // 98

__device__ int g_cnt[NG];
__device__ int g_off[NG];
__device__ int g_bcnt[NB * NG];
__device__ int g_order[NN];
__device__ float g_part[NG * NSEG * 944];

// ─── Sort pass 1: per-block histogram (no global atomics) ───
__global__ void __launch_bounds__(256) k_hist_agg(const int* __restrict__ idx) {
    __shared__ int h[NG];
    const int b = blockIdx.x;
    const int tid = threadIdx.x;
    for (int g = tid; g < NG; g += 256) h[g] = 0;
    __syncthreads();
    const int base = b * CH;
    #pragma unroll
    for (int k = 0; k < CH / 256; k++) {
        int i = base + tid + k * 256;
        if (i < NN) atomicAdd(&h[idx[i]], 1);
    }
    __syncthreads();
    for (int g = tid; g < NG; g += 256) g_bcnt[b * NG + g] = h[g];
}

// ─── Sort pass 2: column prefix over blocks → g_cnt ───
__global__ void __launch_bounds__(500) k_colscan() {
    const int g = blockIdx.x * 500 + threadIdx.x;
    if (g >= NG) return;
    int run = 0;
    #pragma unroll 7
    for (int b = 0; b < NB; b++) {
        int t = g_bcnt[b * NG + g];
        g_bcnt[b * NG + g] = run;
        run += t;
    }
    g_cnt[g] = run;
}

// ─── Sort pass 3: exclusive scan of g_cnt → g_off ───
__global__ void k_scan() {
    __shared__ int s[1024];
    int tid = threadIdx.x;
    int v = (tid < NG) ? g_cnt[tid] : 0;
    s[tid] = v;
    __syncthreads();
    for (int off = 1; off < 1024; off <<= 1) {
        int t = (tid >= off) ? s[tid - off] : 0;
        __syncthreads();
        s[tid] += t;
        __syncthreads();
    }
    if (tid < NG) g_off[tid] = s[tid] - v;
}

// ─── Sort pass 4: scatter using per-block bases (smem atomics only) ───
__global__ void __launch_bounds__(256) k_scatter_det(const int* __restrict__ idx) {
    __shared__ int sbase[NG];
    const int b = blockIdx.x;
    const int tid = threadIdx.x;
    for (int g = tid; g < NG; g += 256)
        sbase[g] = g_off[g] + g_bcnt[b * NG + g];
    __syncthreads();
    const int base = b * CH;
    #pragma unroll
    for (int k = 0; k < CH / 256; k++) {
        int i = base + tid + k * 256;
        if (i < NN) {
            int pos = atomicAdd(&sbase[idx[i]], 1);
            g_order[pos] = i;
        }
    }
}

// ─── Main accumulation ───
// Partial layout (944 floats per (graph, segment)):
//   [0,240) sum(x) | [240,480) sum(x·e^{+n}) | [480,720) sum(x·e^{-n})
//   [720,832) sum(e^{+n}) | [832,944) sum(e^{-n})  (112 irrep instances)
// Warp = one node. Lane L owns feats {L, 32+L}, l1 triple at 64+3L,
// and (L<16) the l2 quintuple at 160+5L.
__global__ void __launch_bounds__(256) k_partial(const float* __restrict__ x)
{
    __shared__ float s_part[8][944];

    const int g = blockIdx.x;
    const int seg = blockIdx.y;
    const int tid = threadIdx.x;
    const int w = tid >> 5;
    const int L = tid & 31;
    const int start = g_off[g];
    const int cnt = g_cnt[g];
    const int j0 = (cnt * seg) / NSEG;
    const int j1 = (cnt * (seg + 1)) / NSEG;
    const bool hd = (L < 16);

    float s0 = 0.f, s1 = 0.f, sc0 = 0.f, sc1 = 0.f, sc2 = 0.f;
    float sd0 = 0.f, sd1 = 0.f, sd2 = 0.f, sd3 = 0.f, sd4 = 0.f;
    float p0 = 0.f, p1 = 0.f, pc0 = 0.f, pc1 = 0.f, pc2 = 0.f;
    float pd0 = 0.f, pd1 = 0.f, pd2 = 0.f, pd3 = 0.f, pd4 = 0.f;
    float m0 = 0.f, m1 = 0.f, mc0 = 0.f, mc1 = 0.f, mc2 = 0.f;
    float md0 = 0.f, md1 = 0.f, md2 = 0.f, md3 = 0.f, md4 = 0.f;
    float zp0 = 0.f, zp1 = 0.f, zpc = 0.f, zpd = 0.f;
    float zm0 = 0.f, zm1 = 0.f, zmc = 0.f, zmd = 0.f;

    int j = j0 + w;
    int node = (j < j1) ? g_order[start + j] : 0;
    while (j < j1) {
        const float* r = x + (long long)node * FEAT;
        const int jn = j + 8;
        const int nnode = (jn < j1) ? g_order[start + jn] : 0;

        float a  = __ldg(r + L);
        float b  = __ldg(r + 32 + L);
        float c0 = __ldg(r + 64 + 3 * L);
        float c1 = __ldg(r + 65 + 3 * L);
        float c2 = __ldg(r + 66 + 3 * L);
        float d0 = 0.f, d1 = 0.f, d2 = 0.f, d3 = 0.f, d4 = 0.f;
        if (hd) {
            const float* q = r + 160 + 5 * L;
            d0 = __ldg(q + 0); d1 = __ldg(q + 1); d2 = __ldg(q + 2);
            d3 = __ldg(q + 3); d4 = __ldg(q + 4);
        }
        float na = fabsf(a), nb = fabsf(b);
        float nc = sqrtf(c0 * c0 + c1 * c1 + c2 * c2);
        float nd = sqrtf(d0 * d0 + d1 * d1 + d2 * d2 + d3 * d3 + d4 * d4);
        float ea = __expf(na),  ra = __expf(-na);
        float eb = __expf(nb),  rb = __expf(-nb);
        float ec = __expf(nc),  rc = __expf(-nc);
        float ed = __expf(nd),  rd = __expf(-nd);

        s0 += a;  s1 += b;
        sc0 += c0; sc1 += c1; sc2 += c2;
        sd0 += d0; sd1 += d1; sd2 += d2; sd3 += d3; sd4 += d4;

        p0 += a * ea;  p1 += b * eb;
        pc0 += c0 * ec; pc1 += c1 * ec; pc2 += c2 * ec;
        pd0 += d0 * ed; pd1 += d1 * ed; pd2 += d2 * ed;
        pd3 += d3 * ed; pd4 += d4 * ed;

        m0 += a * ra;  m1 += b * rb;
        mc0 += c0 * rc; mc1 += c1 * rc; mc2 += c2 * rc;
        md0 += d0 * rd; md1 += d1 * rd; md2 += d2 * rd;
        md3 += d3 * rd; md4 += d4 * rd;

        zp0 += ea; zp1 += eb; zpc += ec; zpd += ed;
        zm0 += ra; zm1 += rb; zmc += rc; zmd += rd;

        j = jn; node = nnode;
    }

    {
        float* P = s_part[w];
        P[L] = s0;  P[32 + L] = s1;
        P[64 + 3 * L + 0] = sc0; P[64 + 3 * L + 1] = sc1; P[64 + 3 * L + 2] = sc2;
        P[240 + L] = p0;  P[272 + L] = p1;
        P[304 + 3 * L + 0] = pc0; P[304 + 3 * L + 1] = pc1; P[304 + 3 * L + 2] = pc2;
        P[480 + L] = m0;  P[512 + L] = m1;
        P[544 + 3 * L + 0] = mc0; P[544 + 3 * L + 1] = mc1; P[544 + 3 * L + 2] = mc2;
        P[720 + L] = zp0; P[752 + L] = zp1; P[784 + L] = zpc;
        P[832 + L] = zm0; P[864 + L] = zm1; P[896 + L] = zmc;
        if (hd) {
            P[160 + 5 * L + 0] = sd0; P[160 + 5 * L + 1] = sd1; P[160 + 5 * L + 2] = sd2;
            P[160 + 5 * L + 3] = sd3; P[160 + 5 * L + 4] = sd4;
            P[400 + 5 * L + 0] = pd0; P[400 + 5 * L + 1] = pd1; P[400 + 5 * L + 2] = pd2;
            P[400 + 5 * L + 3] = pd3; P[400 + 5 * L + 4] = pd4;
            P[640 + 5 * L + 0] = md0; P[640 + 5 * L + 1] = md1; P[640 + 5 * L + 2] = md2;
            P[640 + 5 * L + 3] = md3; P[640 + 5 * L + 4] = md4;
            P[816 + L] = zpd;
            P[928 + L] = zmd;
        }
    }
    __syncthreads();

    float* dst = g_part + (g * NSEG + seg) * 944;
    for (int f = tid; f < 944; f += 256) {
        float acc = 0.f;
        #pragma unroll
        for (int ww = 0; ww < 8; ww++) acc += s_part[ww][f];
        dst[f] = acc;
    }
}

// ─── Finish: combine segments, pools, per-graph o3.Linear ───
__global__ void __launch_bounds__(256) k_finish(
    const float* __restrict__ W0, const float* __restrict__ W1,
    const float* __restrict__ W2, const float* __restrict__ b0,
    float* __restrict__ out)
{
    __shared__ float s_tot[944];
    __shared__ float s_pool[3][240];

    const int g = blockIdx.x;
    const int tid = threadIdx.x;
    const int cnt = g_cnt[g];
    const float* src = g_part + g * NSEG * 944;

    for (int f = tid; f < 944; f += 256) {
        float acc = 0.f;
        #pragma unroll
        for (int s = 0; s < NSEG; s++) acc += src[s * 944 + f];
        s_tot[f] = acc;
    }
    __syncthreads();

    const float invc = (cnt > 0) ? (1.0f / (float)cnt) : 0.0f;
    for (int f = tid; f < 240; f += 256) {
        int k;
        if (f < 64)       k = f;
        else if (f < 160) k = 64 + (f - 64) / 3;
        else              k = 96 + (f - 160) / 5;
        float zp = s_tot[720 + k];
        float zm = s_tot[832 + k];
        float rzp = (zp > 0.f) ? 1.0f / zp : 0.f;
        float rzm = (zm > 0.f) ? 1.0f / zm : 0.f;
        s_pool[0][f] = s_tot[f] * invc;
        s_pool[1][f] = s_tot[240 + f] * rzp;
        s_pool[2][f] = s_tot[480 + f] * rzm;
    }
    __syncthreads();

    if (tid < 240) {
        float o = 0.f;
        if (tid < 64) {
            const int f = tid;
            #pragma unroll 8
            for (int i = 0; i < 64; i++) {
                o += s_pool[0][i] * __ldg(W0 + i * 64 + f);
                o += s_pool[1][i] * __ldg(W0 + (64 + i) * 64 + f);
                o += s_pool[2][i] * __ldg(W0 + (128 + i) * 64 + f);
            }
            o = o * 0.07216878364870323f + __ldg(b0 + f);   // 1/sqrt(192)
            out[g * FEAT + f] = o;
        } else if (tid < 160) {
            const int ff = tid - 64;
            const int oo = ff / 3, dd = ff % 3;
            #pragma unroll 8
            for (int i = 0; i < 32; i++) {
                o += s_pool[0][64 + 3 * i + dd] * __ldg(W1 + i * 32 + oo);
                o += s_pool[1][64 + 3 * i + dd] * __ldg(W1 + (32 + i) * 32 + oo);
                o += s_pool[2][64 + 3 * i + dd] * __ldg(W1 + (64 + i) * 32 + oo);
            }
            out[g * FEAT + tid] = o * 0.10206207261596575f; // 1/sqrt(96)
        } else {
            const int ff = tid - 160;
            const int oo = ff / 5, dd = ff % 5;
            #pragma unroll
            for (int i = 0; i < 16; i++) {
                o += s_pool[0][160 + 5 * i + dd] * __ldg(W2 + i * 16 + oo);
                o += s_pool[1][160 + 5 * i + dd] * __ldg(W2 + (16 + i) * 16 + oo);
                o += s_pool[2][160 + 5 * i + dd] * __ldg(W2 + (32 + i) * 16 + oo);
            }
            out[g * FEAT + tid] = o * 0.14433756729740643f; // 1/sqrt(48)
        }
    }
}

extern "C" void kernel_launch(void* const* d_in, const int* in_sizes, int n_in,
                              void* d_out, int out_size) {
    const float* x = nullptr;
    const int* idx = nullptr;
    const float *W0 = nullptr, *W1 = nullptr, *W2 = nullptr, *b0 = nullptr;
    for (int i = 0; i < n_in; i++) {
        switch (in_sizes[i]) {
            case 96000000: x   = (const float*)d_in[i]; break; // x [400000,240]
            case 400000:   idx = (const int*)d_in[i];   break; // index
            case 12288:    W0  = (const float*)d_in[i]; break; // [192,64]
            case 3072:     W1  = (const float*)d_in[i]; break; // [96,32]
            case 768:      W2  = (const float*)d_in[i]; break; // [48,16]
            case 64:       b0  = (const float*)d_in[i]; break; // [64]
            default: break; // dim_size scalar etc.
        }
    }
    k_hist_agg<<<NB, 256>>>(idx);
    k_colscan<<<2, 500>>>();
    k_scan<<<1, 1024>>>();
    k_scatter_det<<<NB, 256>>>(idx);
    k_partial<<<dim3(NG, NSEG), 256>>>(x);
    k_finish<<<NG, 256>>>(W0, W1, W2, b0, (float*)d_out);
}